// round 3
// baseline (speedup 1.0000x reference)
#include <cuda_runtime.h>
#include <cstdint>

#define K_DET 100
#define NBINS 256
#define CAP 2048
#define M_TARGET 1024
#define CHUNK 128
#define NSLICE 16
#define B_MAX 128

__device__ int    g_hist[B_MAX][NBINS];
__device__ int    g_cnt[B_MAX];
__device__ float4 g_box[B_MAX][CAP];
__device__ float  g_sc[B_MAX][CAP];
__device__ int    g_oi[B_MAX][CAP];

// ---------------- K0: zero per-image hist + count ----------------
__global__ void k_zero() {
    int img = blockIdx.x;
    for (int i = threadIdx.x; i < NBINS; i += blockDim.x) g_hist[img][i] = 0;
    if (threadIdx.x == 0) g_cnt[img] = 0;
}

// ---------------- K1: chip-wide histogram ----------------
__global__ __launch_bounds__(256)
void k_hist(const float* __restrict__ scores, int N) {
    __shared__ int h[NBINS];
    const int img = blockIdx.y, slice = blockIdx.x;
    for (int i = threadIdx.x; i < NBINS; i += 256) h[i] = 0;
    __syncthreads();

    const float* sc = scores + (size_t)img * N;
    int per = ((N + NSLICE - 1) / NSLICE + 3) & ~3;
    int lo = slice * per;
    int hi = min(N, lo + per);
    if (lo < hi) {
        int hi4 = lo + ((hi - lo) & ~3);
        const float4* s4 = (const float4*)sc;
        for (int i = (lo >> 2) + threadIdx.x; i < (hi4 >> 2); i += 256) {
            float4 v = s4[i];
            if (v.x > 0.05f) atomicAdd(&h[min((int)(v.x * 256.0f), 255)], 1);
            if (v.y > 0.05f) atomicAdd(&h[min((int)(v.y * 256.0f), 255)], 1);
            if (v.z > 0.05f) atomicAdd(&h[min((int)(v.z * 256.0f), 255)], 1);
            if (v.w > 0.05f) atomicAdd(&h[min((int)(v.w * 256.0f), 255)], 1);
        }
        for (int i = hi4 + (int)threadIdx.x; i < hi; i += 256) {
            float s = sc[i];
            if (s > 0.05f) atomicAdd(&h[min((int)(s * 256.0f), 255)], 1);
        }
    }
    __syncthreads();
    for (int i = threadIdx.x; i < NBINS; i += 256)
        if (h[i]) atomicAdd(&g_hist[img][i], h[i]);
}

// ---------------- K2: chip-wide compaction of top candidates ----------------
__global__ __launch_bounds__(256)
void k_compact(const float* __restrict__ scores,
               const float* __restrict__ boxes, int N) {
    __shared__ int s_tb;
    const int img = blockIdx.y, slice = blockIdx.x;
    if (threadIdx.x == 0) {
        int cum = 0, b = NBINS - 1;
        for (; b > 0; --b) { cum += g_hist[img][b]; if (cum >= M_TARGET) break; }
        s_tb = b;
    }
    __syncthreads();
    const int tb = s_tb;

    const float* sc = scores + (size_t)img * N;
    const float4* bx = (const float4*)(boxes + (size_t)img * N * 4);

    int per = ((N + NSLICE - 1) / NSLICE + 3) & ~3;
    int lo = slice * per;
    int hi = min(N, lo + per);
    int span = hi > lo ? hi - lo : 0;
    int spanPad = (span + 255) & ~255;

    for (int t = threadIdx.x; t < spanPad; t += 256) {
        int i = lo + t;
        bool pass = false;
        float s = 0.f;
        if (t < span) {
            s = sc[i];
            if (s > 0.05f) {
                int b = min((int)(s * 256.0f), 255);
                pass = (b >= tb);
            }
        }
        unsigned m = __ballot_sync(0xffffffffu, pass);
        if (m) {
            int lane = threadIdx.x & 31;
            int leader = __ffs(m) - 1;
            int base = 0;
            if (lane == leader) base = atomicAdd(&g_cnt[img], __popc(m));
            base = __shfl_sync(0xffffffffu, base, leader);
            if (pass) {
                int pos = base + __popc(m & ((1u << lane) - 1u));
                if (pos < CAP) {
                    g_box[img][pos] = bx[i];
                    g_sc[img][pos]  = s;
                    g_oi[img][pos]  = i;
                }
            }
        }
    }
}

// ---------------- K3: sort + ballot-walk NMS + output ----------------
#define NT3 1024
__global__ __launch_bounds__(NT3, 1)
void k_nms(const int* __restrict__ classes,
           float* __restrict__ out, int B, int N) {
    extern __shared__ float4 smbase[];
    float4* sbox   = smbase;                                    // CAP
    float4* selbox = sbox + CAP;                                // K_DET
    unsigned long long* skey = (unsigned long long*)(selbox + K_DET); // CAP
    float* ssc  = (float*)(skey + CAP);                         // CAP
    int*   soi  = (int*)(ssc + CAP);                            // CAP
    int*   kslot= soi + CAP;                                    // CAP
    float* selsc= (float*)(kslot + CAP);                        // K_DET
    int*   seloi= (int*)(selsc + K_DET);                        // K_DET
    int*   presup = seloi + K_DET;                              // CHUNK
    unsigned* supmask = (unsigned*)(presup + CHUNK);            // CHUNK*4

    __shared__ int s_nsel;

    const int img = blockIdx.x;
    const int tid = threadIdx.x;

    const int C = min(g_cnt[img], CAP);
    if (tid == 0) s_nsel = 0;

    // load candidates into smem
    for (int i = tid; i < C; i += NT3) {
        sbox[i] = g_box[img][i];
        float s = g_sc[img][i];
        int oi  = g_oi[img][i];
        ssc[i] = s;
        soi[i] = oi;
        skey[i] = ((unsigned long long)(~__float_as_uint(s)) << 32) | (unsigned)oi;
        kslot[i] = i;
    }

    int P = 1; while (P < C) P <<= 1;
    for (int t = C + tid; t < P; t += NT3) {
        skey[t] = 0xFFFFFFFFFFFFFFFFULL;
        kslot[t] = -1;
    }
    __syncthreads();

    // bitonic sort ascending (key = score desc, index asc)
    for (int size = 2; size <= P; size <<= 1) {
        for (int stride = size >> 1; stride > 0; stride >>= 1) {
            int half = P >> 1;
            for (int t = tid; t < half; t += NT3) {
                int lo = ((t & ~(stride - 1)) << 1) | (t & (stride - 1));
                int hi = lo + stride;
                bool asc = ((lo & size) == 0);
                unsigned long long a = skey[lo], c = skey[hi];
                if ((a > c) == asc) {
                    skey[lo] = c; skey[hi] = a;
                    int tmp = kslot[lo]; kslot[lo] = kslot[hi]; kslot[hi] = tmp;
                }
            }
            __syncthreads();
        }
    }

    // chunked walk: parallel masks + warp-ballot resolution
    for (int cb = 0; cb < C; cb += CHUNK) {
        if (s_nsel >= K_DET) break;
        const int cl_n = min(CHUNK, C - cb);

        if (tid < CHUNK) presup[tid] = 0;
        if (tid < CHUNK * 4) supmask[tid] = 0;
        __syncthreads();

        const int ns0 = s_nsel;
        // pre-suppression vs already-selected boxes
        {
            int c = tid >> 3, k = tid & 7;
            if (c < cl_n) {
                float4 bc = sbox[kslot[cb + c]];
                float areac = (bc.z - bc.x) * (bc.w - bc.y);
                for (int s = k; s < ns0; s += 8) {
                    float4 bs = selbox[s];
                    float xx1 = fmaxf(bs.x, bc.x), yy1 = fmaxf(bs.y, bc.y);
                    float xx2 = fminf(bs.z, bc.z), yy2 = fminf(bs.w, bc.w);
                    float inter = fmaxf(xx2 - xx1, 0.f) * fmaxf(yy2 - yy1, 0.f);
                    float areas_ = (bs.z - bs.x) * (bs.w - bs.y);
                    float iou = inter / (areas_ + areac - inter + 1e-6f);
                    if (iou > 0.5f) { presup[c] = 1; break; }
                }
            }
        }
        // intra-chunk pairwise: i (earlier) suppresses j
        {
            int j = tid >> 3, k = tid & 7;
            if (j > 0 && j < cl_n) {
                float4 bj = sbox[kslot[cb + j]];
                float areaj = (bj.z - bj.x) * (bj.w - bj.y);
                for (int i = k; i < j; i += 8) {
                    float4 bi = sbox[kslot[cb + i]];
                    float xx1 = fmaxf(bi.x, bj.x), yy1 = fmaxf(bi.y, bj.y);
                    float xx2 = fminf(bi.z, bj.z), yy2 = fminf(bi.w, bj.w);
                    float inter = fmaxf(xx2 - xx1, 0.f) * fmaxf(yy2 - yy1, 0.f);
                    float areai = (bi.z - bi.x) * (bi.w - bi.y);
                    float iou = inter / (areai + areaj - inter + 1e-6f);
                    if (iou > 0.5f)
                        atomicOr(&supmask[(j << 2) + (i >> 5)], 1u << (i & 31));
                }
            }
        }
        __syncthreads();

        // warp-0 ballot resolution: one iteration per SELECTION
        if (tid < 32) {
            const int lane = tid;
            unsigned mr[4][4];
            bool alive[4];
            #pragma unroll
            for (int q = 0; q < 4; ++q) {
                int c = q * 32 + lane;
                #pragma unroll
                for (int w = 0; w < 4; ++w) mr[q][w] = supmask[(c << 2) + w];
                alive[q] = (c < cl_n) && (presup[c] == 0);
            }
            int ns = ns0;
            while (ns < K_DET) {
                int c = -1;
                #pragma unroll
                for (int q = 0; q < 4; ++q) {
                    unsigned b = __ballot_sync(0xffffffffu, alive[q]);
                    if (c < 0 && b) c = q * 32 + (__ffs(b) - 1);
                }
                if (c < 0) break;
                int cq = c >> 5, cbit = c & 31;
                if (lane == cbit) {
                    alive[cq] = false;
                    int sl = kslot[cb + c];
                    selbox[ns] = sbox[sl];
                    selsc[ns]  = ssc[sl];
                    seloi[ns]  = soi[sl];
                }
                #pragma unroll
                for (int q = 0; q < 4; ++q)
                    if ((mr[q][cq] >> cbit) & 1u) alive[q] = false;
                ns++;
            }
            if (lane == 0) s_nsel = ns;
        }
        __syncthreads();
    }

    // outputs: idx | scores | boxes | classes | num_valid
    const int nsel = s_nsel;
    const int* cls_in = classes + (size_t)img * N;
    const size_t BK = (size_t)B * K_DET;
    for (int t = tid; t < K_DET; t += NT3) {
        size_t r = (size_t)img * K_DET + t;
        if (t < nsel) {
            int oi = seloi[t];
            out[r]      = (float)oi;
            out[BK + r] = selsc[t];
            float4 b4 = selbox[t];
            out[2 * BK + 4 * r + 0] = b4.x;
            out[2 * BK + 4 * r + 1] = b4.y;
            out[2 * BK + 4 * r + 2] = b4.z;
            out[2 * BK + 4 * r + 3] = b4.w;
            out[6 * BK + r] = (float)cls_in[oi];
        } else {
            out[r]      = -1.f;
            out[BK + r] = 0.f;
            out[2 * BK + 4 * r + 0] = 0.f;
            out[2 * BK + 4 * r + 1] = 0.f;
            out[2 * BK + 4 * r + 2] = 0.f;
            out[2 * BK + 4 * r + 3] = 0.f;
            out[6 * BK + r] = -1.f;
        }
    }
    if (tid == 0) out[7 * BK + img] = (float)nsel;
}

extern "C" void kernel_launch(void* const* d_in, const int* in_sizes, int n_in,
                              void* d_out, int out_size) {
    const float* scores  = (const float*)d_in[0];
    const float* boxes   = (const float*)d_in[1];
    const int*   classes = (const int*)d_in[2];
    float* out = (float*)d_out;

    int B = out_size / (7 * K_DET + 1);
    if (B < 1) B = 1;
    if (B > B_MAX) B = B_MAX;
    int N = in_sizes[0] / B;

    size_t smem3 = (size_t)CAP * 16       // sbox
                 + (size_t)K_DET * 16     // selbox
                 + (size_t)CAP * 8        // skey
                 + (size_t)CAP * 4 * 3    // ssc, soi, kslot
                 + (size_t)K_DET * 4 * 2  // selsc, seloi
                 + (size_t)CHUNK * 4      // presup
                 + (size_t)CHUNK * 16;    // supmask

    cudaFuncSetAttribute(k_nms, cudaFuncAttributeMaxDynamicSharedMemorySize,
                         (int)smem3);

    dim3 gscan(NSLICE, B);
    k_zero<<<B, 256>>>();
    k_hist<<<gscan, 256>>>(scores, N);
    k_compact<<<gscan, 256>>>(scores, boxes, N);
    k_nms<<<B, NT3, smem3>>>(classes, out, B, N);
}